// round 11
// baseline (speedup 1.0000x reference)
#include <cuda_runtime.h>

typedef unsigned long long ull;

#define TLEN 4000
#define HID  64
#define NTHR 384

__device__ __forceinline__ void ffma2(ull &d, ull a, ull b) {
    asm("fma.rn.f32x2 %0, %1, %2, %0;" : "+l"(d) : "l"(a), "l"(b));
}
__device__ __forceinline__ float2 unpack2(ull v) {
    float2 r;
    asm("mov.b64 {%0, %1}, %2;" : "=f"(r.x), "=f"(r.y) : "l"(v));
    return r;
}
__device__ __forceinline__ ull pack2(float x, float y) {
    ull r;
    asm("mov.b64 %0, {%1, %2};" : "=l"(r) : "f"(x), "f"(y));
    return r;
}
__device__ __forceinline__ float hsum2(ull a, ull b) {
    ull s;
    asm("add.rn.f32x2 %0, %1, %2;" : "=l"(s) : "l"(a), "l"(b));
    float2 f = unpack2(s);
    return f.x + f.y;
}
__device__ __forceinline__ float tanha(float x) {
    float r;
    asm("tanh.approx.f32 %0, %1;" : "=f"(r) : "f"(x));
    return r;
}
__device__ __forceinline__ float fsigmoid(float x) {
    return fmaf(tanha(0.5f * x), 0.5f, 0.5f);
}

__global__ void __launch_bounds__(NTHR, 1)
lstm2_ls(const float* __restrict__ x,
         const float* __restrict__ W_ih0,
         const float* __restrict__ W_hh0,
         const float* __restrict__ b_ih0,
         const float* __restrict__ b_hh0,
         const float* __restrict__ W_ih1,
         const float* __restrict__ W_hh1,
         const float* __restrict__ b_ih1,
         const float* __restrict__ b_hh1,
         const float* __restrict__ W_fc,
         const float* __restrict__ b_fc,
         float* __restrict__ out)
{
    __shared__ __align__(16) float  sh_x[2 * TLEN];       // 32 KB staged input
    __shared__ __align__(16) float  sh_h[2][2][2 * HID];  // [slot][batch][h0|h1]
    __shared__ __align__(16) float4 sh_gA[4][32];         // layer0 gates
    __shared__ __align__(16) float2 sh_gB[8][32];         // layer1 gates

    const int tid   = threadIdx.x;
    const int wid   = tid >> 5;
    const int l     = tid & 31;
    const int bbase = blockIdx.x * 2;

    // Stage x (two contiguous batch rows)
    {
        const float4* xg = (const float4*)(x + (size_t)bbase * TLEN);
        float4* xs = (float4*)sh_x;
        for (int i = tid; i < 2 * TLEN / 4; i += NTHR) xs[i] = xg[i];
    }
    for (int i = tid; i < 2 * 2 * 2 * HID; i += NTHR) ((float*)sh_h)[i] = 0.0f;

    if (wid < 4) {
        // ========== LAYER-0 warps: 2 W_hh0 rows each ==========
        const int w  = wid;
        const int q  = l >> 3;          // gate
        const int j  = l & 7;
        const int ra = 64 * q + 16 * w + j;       // row a
        const int rb = 64 * q + 16 * w + 8 + j;   // row b
        ull wa[32], wb[32];
        {
            const ulonglong2* p = (const ulonglong2*)(W_hh0 + ra * HID);
            #pragma unroll
            for (int t = 0; t < 16; t++) { ulonglong2 v = p[t]; wa[2*t] = v.x; wa[2*t+1] = v.y; }
            p = (const ulonglong2*)(W_hh0 + rb * HID);
            #pragma unroll
            for (int t = 0; t < 16; t++) { ulonglong2 v = p[t]; wb[2*t] = v.x; wb[2*t+1] = v.y; }
        }
        const float wxa = W_ih0[ra], wxb = W_ih0[rb];
        const float bAa = b_ih0[ra] + b_hh0[ra];
        const float bAb = b_ih0[rb] + b_hh0[rb];

        // pw item: unit uP = 16w + (l&15), batch bP = l>>4
        const int vP = l & 15;
        const int uP = 16 * w + vP;
        const int bP = l >> 4;
        const int hb = ((l >> 3) & 1) * 2 + bP;   // float4 component selector
        const float* gp = (const float*)&sh_gA[w][0];
        const int v8 = vP & 7;
        float c = 0.0f;

        __syncthreads();

        for (int k = 0; k <= TLEN; ++k) {
            const int rs = (k + 1) & 1;
            const int ws = k & 1;
            if (k < TLEN) {
                const ulonglong2* h0b0 = (const ulonglong2*)&sh_h[rs][0][0];
                const ulonglong2* h0b1 = (const ulonglong2*)&sh_h[rs][1][0];
                const float xa = sh_x[k], xb = sh_x[TLEN + k];
                ull aa0x = pack2(fmaf(xa, wxa, bAa), 0.0f), aa0y = 0ull;
                ull aa1x = pack2(fmaf(xb, wxa, bAa), 0.0f), aa1y = 0ull;
                ull ab0x = pack2(fmaf(xa, wxb, bAb), 0.0f), ab0y = 0ull;
                ull ab1x = pack2(fmaf(xb, wxb, bAb), 0.0f), ab1y = 0ull;
                #pragma unroll
                for (int t = 0; t < 16; t++) {
                    ulonglong2 v0 = h0b0[t], v1 = h0b1[t];
                    ffma2(aa0x, wa[2*t],   v0.x);
                    ffma2(aa1x, wa[2*t],   v1.x);
                    ffma2(ab0x, wb[2*t],   v0.x);
                    ffma2(ab1x, wb[2*t],   v1.x);
                    ffma2(aa0y, wa[2*t+1], v0.y);
                    ffma2(aa1y, wa[2*t+1], v1.y);
                    ffma2(ab0y, wb[2*t+1], v0.y);
                    ffma2(ab1y, wb[2*t+1], v1.y);
                }
                sh_gA[w][l] = make_float4(hsum2(aa0x, aa0y), hsum2(aa1x, aa1y),
                                          hsum2(ab0x, ab0y), hsum2(ab1x, ab1y));
            }
            __syncwarp();
            if (k < TLEN) {   // pw layer0 -> h0(k)
                float g_i = gp[(0*8 + v8)*4 + hb];
                float g_f = gp[(1*8 + v8)*4 + hb];
                float g_c = gp[(2*8 + v8)*4 + hb];
                float g_o = gp[(3*8 + v8)*4 + hb];
                float iv = fsigmoid(g_i), fv = fsigmoid(g_f), ov = fsigmoid(g_o);
                float cv = tanha(g_c);
                c = fmaf(fv, c, iv * cv);
                sh_h[ws][bP][uP] = ov * tanha(c);
            }
            __syncthreads();
        }
    } else {
        // ========== LAYER-1 warps: one [W_ih1|W_hh1] row each ==========
        const int w1 = wid - 4;          // 0..7
        const int q  = l >> 3;
        const int j  = l & 7;
        const int u  = 8 * w1 + j;
        const int row = 64 * q + u;
        ull wI[32], wH[32];
        {
            const ulonglong2* p = (const ulonglong2*)(W_ih1 + row * HID);
            #pragma unroll
            for (int t = 0; t < 16; t++) { ulonglong2 v = p[t]; wI[2*t] = v.x; wI[2*t+1] = v.y; }
            p = (const ulonglong2*)(W_hh1 + row * HID);
            #pragma unroll
            for (int t = 0; t < 16; t++) { ulonglong2 v = p[t]; wH[2*t] = v.x; wH[2*t+1] = v.y; }
        }
        const float biasB = b_ih1[row] + b_hh1[row];

        // pw item (lanes q<2): unit u, batch bP = q
        const bool pwact = (q < 2);
        const int bP = q & 1;
        const float* gp = (const float*)&sh_gB[w1][0];
        float c = 0.0f;

        __syncthreads();

        for (int k = 0; k <= TLEN; ++k) {
            const int rs = (k + 1) & 1;
            const int ws = k & 1;
            if (k >= 1) {   // gB(k-1) = wI·h0(k-1) + wH·h1(k-2)
                const ulonglong2* h0b0 = (const ulonglong2*)&sh_h[rs][0][0];
                const ulonglong2* h0b1 = (const ulonglong2*)&sh_h[rs][1][0];
                const ulonglong2* h1b0 = (const ulonglong2*)&sh_h[rs][0][HID];
                const ulonglong2* h1b1 = (const ulonglong2*)&sh_h[rs][1][HID];
                ull a0x = pack2(biasB, 0.0f), a0y = 0ull;
                ull a1x = a0x,                a1y = 0ull;
                #pragma unroll
                for (int t = 0; t < 16; t++) {
                    ulonglong2 v0 = h0b0[t], v1 = h0b1[t];
                    ffma2(a0x, wI[2*t],   v0.x);
                    ffma2(a1x, wI[2*t],   v1.x);
                    ffma2(a0y, wI[2*t+1], v0.y);
                    ffma2(a1y, wI[2*t+1], v1.y);
                }
                #pragma unroll
                for (int t = 0; t < 16; t++) {
                    ulonglong2 v0 = h1b0[t], v1 = h1b1[t];
                    ffma2(a0x, wH[2*t],   v0.x);
                    ffma2(a1x, wH[2*t],   v1.x);
                    ffma2(a0y, wH[2*t+1], v0.y);
                    ffma2(a1y, wH[2*t+1], v1.y);
                }
                sh_gB[w1][l] = make_float2(hsum2(a0x, a0y), hsum2(a1x, a1y));
            }
            __syncwarp();
            if (pwact && k >= 1) {   // pw layer1 -> h1(k-1)
                float g_i = gp[(0*8 + j)*2 + bP];
                float g_f = gp[(1*8 + j)*2 + bP];
                float g_c = gp[(2*8 + j)*2 + bP];
                float g_o = gp[(3*8 + j)*2 + bP];
                float iv = fsigmoid(g_i), fv = fsigmoid(g_f), ov = fsigmoid(g_o);
                float cv = tanha(g_c);
                c = fmaf(fv, c, iv * cv);
                sh_h[ws][bP][HID + u] = ov * tanha(c);
            }
            __syncthreads();
        }
    }

    // ---- FC head on final h1 (h1(TLEN-1) written at k=TLEN -> slot 0) ----
    if (tid < 256) {
        const int e  = tid & 127;
        const int bb = tid >> 7;
        float acc = b_fc[e];
        const float* wr = W_fc + e * HID;
        const float* hv = &sh_h[0][bb][HID];
        #pragma unroll
        for (int t = 0; t < HID; t += 4) {
            acc = fmaf(wr[t],     hv[t],     acc);
            acc = fmaf(wr[t + 1], hv[t + 1], acc);
            acc = fmaf(wr[t + 2], hv[t + 2], acc);
            acc = fmaf(wr[t + 3], hv[t + 3], acc);
        }
        out[(size_t)(bbase + bb) * 128 + e] = acc;
    }
}

extern "C" void kernel_launch(void* const* d_in, const int* in_sizes, int n_in,
                              void* d_out, int out_size) {
    (void)in_sizes; (void)n_in; (void)out_size;
    lstm2_ls<<<128, NTHR>>>(
        (const float*)d_in[0],   // x
        (const float*)d_in[1],   // W_ih0
        (const float*)d_in[2],   // W_hh0
        (const float*)d_in[3],   // b_ih0
        (const float*)d_in[4],   // b_hh0
        (const float*)d_in[5],   // W_ih1
        (const float*)d_in[6],   // W_hh1
        (const float*)d_in[7],   // b_ih1
        (const float*)d_in[8],   // b_hh1
        (const float*)d_in[9],   // W_fc
        (const float*)d_in[10],  // b_fc
        (float*)d_out);
}

// round 12
// speedup vs baseline: 1.1006x; 1.1006x over previous
#include <cuda_runtime.h>

typedef unsigned long long ull;

#define TLEN 4000
#define HID  64
#define NTHR 256

__device__ __forceinline__ void ffma2(ull &d, ull a, ull b) {
    asm("fma.rn.f32x2 %0, %1, %2, %0;" : "+l"(d) : "l"(a), "l"(b));
}
__device__ __forceinline__ float2 unpack2(ull v) {
    float2 r;
    asm("mov.b64 {%0, %1}, %2;" : "=f"(r.x), "=f"(r.y) : "l"(v));
    return r;
}
__device__ __forceinline__ ull pack2(float x, float y) {
    ull r;
    asm("mov.b64 %0, {%1, %2};" : "=l"(r) : "f"(x), "f"(y));
    return r;
}
__device__ __forceinline__ float hsum2(ull a, ull b) {
    ull s;
    asm("add.rn.f32x2 %0, %1, %2;" : "=l"(s) : "l"(a), "l"(b));
    float2 f = unpack2(s);
    return f.x + f.y;
}
__device__ __forceinline__ float tanha(float x) {
    float r;
    asm("tanh.approx.f32 %0, %1;" : "=f"(r) : "f"(x));
    return r;
}
__device__ __forceinline__ float fsigmoid(float x) {
    return fmaf(tanha(0.5f * x), 0.5f, 0.5f);
}

__global__ void __launch_bounds__(NTHR, 1)
lstm2_r12(const float* __restrict__ x,
          const float* __restrict__ W_ih0,
          const float* __restrict__ W_hh0,
          const float* __restrict__ b_ih0,
          const float* __restrict__ b_hh0,
          const float* __restrict__ W_ih1,
          const float* __restrict__ W_hh1,
          const float* __restrict__ b_ih1,
          const float* __restrict__ b_hh1,
          const float* __restrict__ W_fc,
          const float* __restrict__ b_fc,
          float* __restrict__ out)
{
    __shared__ __align__(16) float sh_x[2 * TLEN];       // 32 KB staged input
    __shared__ __align__(16) float sh_h[2][2][2 * HID];  // [slot][batch][h0|h1]
    // Transposed gate exchange: [warp][combo][unit][gate] -> consumer LDS.128
    __shared__ __align__(16) float sh_t[8][4][8][4];

    const int tid   = threadIdx.x;
    const int w     = tid >> 5;
    const int l     = tid & 31;
    const int j     = l & 7;          // unit-local
    const int q     = l >> 3;         // producer gate AND consumer combo
    const int u     = 8 * w + j;      // unit 0..63
    const int row   = 64 * q + u;     // gate row this thread owns
    const int bbase = blockIdx.x * 2;

    // Stage x (two contiguous batch rows)
    {
        const float4* xg = (const float4*)(x + (size_t)bbase * TLEN);
        float4* xs = (float4*)sh_x;
        for (int i = tid; i < 2 * TLEN / 4; i += NTHR) xs[i] = xg[i];
    }
    ((float2*)sh_h)[tid] = make_float2(0.0f, 0.0f);   // zero both slots

    // Per-thread weight rows in registers (packed f32 pairs).
    ull wA[32], wI[32], wH[32];   // W_hh0 / W_ih1 / W_hh1 row `row`
    {
        const ulonglong2* p = (const ulonglong2*)(W_hh0 + row * HID);
        #pragma unroll
        for (int t = 0; t < 16; t++) { ulonglong2 v = p[t]; wA[2*t] = v.x; wA[2*t+1] = v.y; }
        p = (const ulonglong2*)(W_ih1 + row * HID);
        #pragma unroll
        for (int t = 0; t < 16; t++) { ulonglong2 v = p[t]; wI[2*t] = v.x; wI[2*t+1] = v.y; }
        p = (const ulonglong2*)(W_hh1 + row * HID);
        #pragma unroll
        for (int t = 0; t < 16; t++) { ulonglong2 v = p[t]; wH[2*t] = v.x; wH[2*t+1] = v.y; }
    }
    const float wx    = W_ih0[row];
    const float biasA = b_ih0[row] + b_hh0[row];
    const float biasB = b_ih1[row] + b_hh1[row];

    // Consumer combo q: (layer Lq = q>>1, batch bq = q&1), unit u.
    const int Lq = q >> 1;
    const int bq = q & 1;
    const int hoff = Lq * HID + u;
    float c = 0.0f;

    __syncthreads();

    // ---- peel k=0: gA is bias + x term; layer0 pointwise only ----
    {
        float ga0 = fmaf(sh_x[0],    wx, biasA);
        float ga1 = fmaf(sh_x[TLEN], wx, biasA);
        sh_t[w][0][j][q] = ga0;
        sh_t[w][1][j][q] = ga1;
        __syncwarp();
        if (q < 2) {
            float4 gv = *(const float4*)&sh_t[w][q][j][0];
            float iv = fsigmoid(gv.x), fv = fsigmoid(gv.y), ov = fsigmoid(gv.w);
            float cv = tanha(gv.z);
            c = fmaf(fv, c, iv * cv);
            sh_h[0][bq][hoff] = ov * tanha(c);    // h0(0) -> slot 0
        }
        __syncthreads();
    }

    // ---- main loop k = 1 .. TLEN-1: guard-free ----
    for (int k = 1; k < TLEN; ++k) {
        const int rs = (k + 1) & 1;   // slot holding h0(k-1), h1(k-2)
        const int ws = k & 1;         // slot receiving h0(k), h1(k-1)

        const ulonglong2* h0b0 = (const ulonglong2*)&sh_h[rs][0][0];
        const ulonglong2* h0b1 = (const ulonglong2*)&sh_h[rs][1][0];
        const ulonglong2* h1b0 = (const ulonglong2*)&sh_h[rs][0][HID];
        const ulonglong2* h1b1 = (const ulonglong2*)&sh_h[rs][1][HID];

        ull aA0x = pack2(fmaf(sh_x[k], wx, biasA), 0.0f),        aA0y = 0ull;
        ull aA1x = pack2(fmaf(sh_x[TLEN + k], wx, biasA), 0.0f), aA1y = 0ull;
        ull aB0x = pack2(biasB, 0.0f), aB0y = 0ull;
        ull aB1x = aB0x,               aB1y = 0ull;

        if (w < 4) {
            // h0 loop first: wA (layer0) + wI (layer1-ih), shared h0 loads
            #pragma unroll
            for (int t = 0; t < 16; t++) {
                ulonglong2 v0 = h0b0[t], v1 = h0b1[t];
                ffma2(aA0x, wA[2*t],   v0.x);
                ffma2(aA1x, wA[2*t],   v1.x);
                ffma2(aB0x, wI[2*t],   v0.x);
                ffma2(aB1x, wI[2*t],   v1.x);
                ffma2(aA0y, wA[2*t+1], v0.y);
                ffma2(aA1y, wA[2*t+1], v1.y);
                ffma2(aB0y, wI[2*t+1], v0.y);
                ffma2(aB1y, wI[2*t+1], v1.y);
            }
            sh_t[w][0][j][q] = hsum2(aA0x, aA0y);
            sh_t[w][1][j][q] = hsum2(aA1x, aA1y);
            #pragma unroll
            for (int t = 0; t < 16; t++) {
                ulonglong2 v0 = h1b0[t], v1 = h1b1[t];
                ffma2(aB0x, wH[2*t],   v0.x);
                ffma2(aB1x, wH[2*t],   v1.x);
                ffma2(aB0y, wH[2*t+1], v0.y);
                ffma2(aB1y, wH[2*t+1], v1.y);
            }
            sh_t[w][2][j][q] = hsum2(aB0x, aB0y);
            sh_t[w][3][j][q] = hsum2(aB1x, aB1y);
        } else {
            // staggered: h1 loop first to de-burst the smem crossbar
            #pragma unroll
            for (int t = 0; t < 16; t++) {
                ulonglong2 v0 = h1b0[t], v1 = h1b1[t];
                ffma2(aB0x, wH[2*t],   v0.x);
                ffma2(aB1x, wH[2*t],   v1.x);
                ffma2(aB0y, wH[2*t+1], v0.y);
                ffma2(aB1y, wH[2*t+1], v1.y);
            }
            #pragma unroll
            for (int t = 0; t < 16; t++) {
                ulonglong2 v0 = h0b0[t], v1 = h0b1[t];
                ffma2(aA0x, wA[2*t],   v0.x);
                ffma2(aA1x, wA[2*t],   v1.x);
                ffma2(aB0x, wI[2*t],   v0.x);
                ffma2(aB1x, wI[2*t],   v1.x);
                ffma2(aA0y, wA[2*t+1], v0.y);
                ffma2(aA1y, wA[2*t+1], v1.y);
                ffma2(aB0y, wI[2*t+1], v0.y);
                ffma2(aB1y, wI[2*t+1], v1.y);
            }
            sh_t[w][0][j][q] = hsum2(aA0x, aA0y);
            sh_t[w][1][j][q] = hsum2(aA1x, aA1y);
            sh_t[w][2][j][q] = hsum2(aB0x, aB0y);
            sh_t[w][3][j][q] = hsum2(aB1x, aB1y);
        }
        __syncwarp();

        // pointwise: one combo per lane, single LDS.128 for all 4 gates
        {
            float4 gv = *(const float4*)&sh_t[w][q][j][0];
            float iv = fsigmoid(gv.x), fv = fsigmoid(gv.y), ov = fsigmoid(gv.w);
            float cv = tanha(gv.z);
            c = fmaf(fv, c, iv * cv);
            sh_h[ws][bq][hoff] = ov * tanha(c);   // h0(k) / h1(k-1)
        }
        __syncthreads();
    }

    // ---- tail: gB(TLEN-1) only, then layer1 pointwise -> h1(TLEN-1) ----
    {
        // reads h0(TLEN-1), h1(TLEN-2) -- both in slot (TLEN-1)&1 = 1
        const ulonglong2* h0b0 = (const ulonglong2*)&sh_h[1][0][0];
        const ulonglong2* h0b1 = (const ulonglong2*)&sh_h[1][1][0];
        const ulonglong2* h1b0 = (const ulonglong2*)&sh_h[1][0][HID];
        const ulonglong2* h1b1 = (const ulonglong2*)&sh_h[1][1][HID];
        ull aB0x = pack2(biasB, 0.0f), aB0y = 0ull;
        ull aB1x = aB0x,               aB1y = 0ull;
        #pragma unroll
        for (int t = 0; t < 16; t++) {
            ulonglong2 v0 = h0b0[t], v1 = h0b1[t];
            ffma2(aB0x, wI[2*t],   v0.x);
            ffma2(aB1x, wI[2*t],   v1.x);
            ffma2(aB0y, wI[2*t+1], v0.y);
            ffma2(aB1y, wI[2*t+1], v1.y);
        }
        #pragma unroll
        for (int t = 0; t < 16; t++) {
            ulonglong2 v0 = h1b0[t], v1 = h1b1[t];
            ffma2(aB0x, wH[2*t],   v0.x);
            ffma2(aB1x, wH[2*t],   v1.x);
            ffma2(aB0y, wH[2*t+1], v0.y);
            ffma2(aB1y, wH[2*t+1], v1.y);
        }
        sh_t[w][2][j][q] = hsum2(aB0x, aB0y);
        sh_t[w][3][j][q] = hsum2(aB1x, aB1y);
        __syncwarp();
        if (q >= 2) {
            float4 gv = *(const float4*)&sh_t[w][q][j][0];
            float iv = fsigmoid(gv.x), fv = fsigmoid(gv.y), ov = fsigmoid(gv.w);
            float cv = tanha(gv.z);
            c = fmaf(fv, c, iv * cv);
            sh_h[0][bq][HID + u] = ov * tanha(c);   // h1(TLEN-1) -> slot 0
        }
        __syncthreads();
    }

    // ---- FC head on final h1 (slot 0) ----
    {
        const int e  = tid & 127;
        const int bb = tid >> 7;
        float acc = b_fc[e];
        const float* wr = W_fc + e * HID;
        const float* hv = &sh_h[0][bb][HID];
        #pragma unroll
        for (int t = 0; t < HID; t += 4) {
            acc = fmaf(wr[t],     hv[t],     acc);
            acc = fmaf(wr[t + 1], hv[t + 1], acc);
            acc = fmaf(wr[t + 2], hv[t + 2], acc);
            acc = fmaf(wr[t + 3], hv[t + 3], acc);
        }
        out[(size_t)(bbase + bb) * 128 + e] = acc;
    }
}

extern "C" void kernel_launch(void* const* d_in, const int* in_sizes, int n_in,
                              void* d_out, int out_size) {
    (void)in_sizes; (void)n_in; (void)out_size;
    lstm2_r12<<<128, NTHR>>>(
        (const float*)d_in[0],   // x
        (const float*)d_in[1],   // W_ih0
        (const float*)d_in[2],   // W_hh0
        (const float*)d_in[3],   // b_ih0
        (const float*)d_in[4],   // b_hh0
        (const float*)d_in[5],   // W_ih1
        (const float*)d_in[6],   // W_hh1
        (const float*)d_in[7],   // b_ih1
        (const float*)d_in[8],   // b_hh1
        (const float*)d_in[9],   // W_fc
        (const float*)d_in[10],  // b_fc
        (float*)d_out);
}